// round 15
// baseline (speedup 1.0000x reference)
#include <cuda_runtime.h>
#include <cstdint>

// Skinny GEMM via mma.sync tf32 with 2-way K-split warp doubling.
// C[65536,40] = embs[65536,1024] @ Wall^T, Wall = packed [W_status;W_flight;0]
// R15 thesis: every prior variant had 2048 warps total (13.8/SM) fixed by the
// 32-tokens-per-warp tiling; latency-bound equilibrium pins BW at ~12 B/cyc/SM.
// Splitting K across 2 warps per token-group doubles warps (27.7/SM, 24
// resident) with UNCHANGED per-token A and B traffic (unlike mt=1 which
// doubled B). Mainloop = proven barrier-free direct-LDG (R6/R8). Epilogue
// reduces the two K-half partials in smem, then fused dual softmax.
// Raw fp32 bits as tf32 (RZ truncate); linear bias cancelled by corr.

#define EMB    1024
#define NS     5
#define NF     30
#define NL     35
#define NROWS  40
#define OUTC   63
#define BM     128
#define NTH    256
#define LSTR   41
#define NKB    32      // k16 blocks per K-half (512/16)

__device__ float Wall[NROWS * EMB];   // 160KB packed weights (+zero pad rows)

__global__ void pack_w_kernel(const float* __restrict__ Ws,
                              const float* __restrict__ Wf) {
    int i = blockIdx.x * blockDim.x + threadIdx.x;
    if (i < NROWS * EMB) {
        int row = i >> 10, col = i & (EMB - 1);
        float v = 0.0f;
        if (row < NS)      v = Ws[row * EMB + col];
        else if (row < NL) v = Wf[(row - NS) * EMB + col];
        Wall[i] = v;
    }
}

__device__ __forceinline__ void mma8(float* c, const uint32_t* a, const uint32_t* b) {
    asm volatile(
        "mma.sync.aligned.m16n8k8.row.col.f32.tf32.tf32.f32 "
        "{%0,%1,%2,%3}, {%4,%5,%6,%7}, {%8,%9}, {%0,%1,%2,%3};"
        : "+f"(c[0]), "+f"(c[1]), "+f"(c[2]), "+f"(c[3])
        : "r"(a[0]), "r"(a[1]), "r"(a[2]), "r"(a[3]), "r"(b[0]), "r"(b[1]));
}

__global__ __launch_bounds__(NTH, 3) void aux2_ksplit_kernel(
    const float* __restrict__ embs,
    const float* __restrict__ b_status,
    const float* __restrict__ b_flight,
    float* __restrict__ out,
    int ntok)
{
    __shared__ float Ls[BM * LSTR];   // 21KB -> 3 CTAs/SM, L1D stays large

    const int tid  = threadIdx.x;
    const int wid  = tid >> 5;
    const int lane = tid & 31;
    const int g    = lane >> 2;     // 0..7
    const int t    = lane & 3;      // 0..3
    const int tg   = wid & 3;       // token group 0..3 (32 tokens each)
    const int kh   = wid >> 2;      // K-half 0..1 (512 floats each)
    const long tokw = (long)blockIdx.x * BM + tg * 32;

    // A fragments: rows tokw + r*8 + g, cols kh*512 + kb*16 + 4t..
    const float* Abase = embs + (tokw + g) * EMB + kh * 512 + 4 * t;
    // B: packed Wall, rows nt*8 + g (immediate offsets), same K-half
    const float* Bbase = Wall + g * EMB + kh * 512 + 4 * t;

    float acc[2][5][4];
#pragma unroll
    for (int mt = 0; mt < 2; ++mt)
#pragma unroll
        for (int nt = 0; nt < 5; ++nt)
#pragma unroll
            for (int i = 0; i < 4; ++i) acc[mt][nt][i] = 0.0f;

    // ---- barrier-free mainloop: 32 k16 blocks over this warp's K-half ----
#pragma unroll 2
    for (int kb = 0; kb < NKB; ++kb) {
        uint4 a[4];
#pragma unroll
        for (int r = 0; r < 4; ++r)
            a[r] = *(const uint4*)(Abase + r * 8 * EMB + kb * 16);

        // K-permutation: slots {t,t+4} = cols {4t,4t+1}; then {4t+2,4t+3}
        uint32_t af0[2][4] = {
            { a[0].x, a[1].x, a[0].y, a[1].y },
            { a[2].x, a[3].x, a[2].y, a[3].y } };
        uint32_t af1[2][4] = {
            { a[0].z, a[1].z, a[0].w, a[1].w },
            { a[2].z, a[3].z, a[2].w, a[3].w } };

#pragma unroll
        for (int nt = 0; nt < 5; ++nt) {
            uint4 b = *(const uint4*)(Bbase + nt * 8 * EMB + kb * 16);
            uint32_t bf0[2] = { b.x, b.y };
            uint32_t bf1[2] = { b.z, b.w };
#pragma unroll
            for (int mt = 0; mt < 2; ++mt) {
                mma8(acc[mt][nt], af0[mt], bf0);
                mma8(acc[mt][nt], af1[mt], bf1);
            }
        }
    }

    // ---- reduce K-half partials in smem ----
    // pass 1: kh==0 warps write their fragments
    if (kh == 0) {
#pragma unroll
        for (int mt = 0; mt < 2; ++mt)
#pragma unroll
            for (int nt = 0; nt < 5; ++nt) {
                int r0 = tg * 32 + mt * 16 + g;
                int cc = nt * 8 + t * 2;
                if (cc < NL) {
                    Ls[r0 * LSTR + cc]       = acc[mt][nt][0];
                    Ls[(r0 + 8) * LSTR + cc] = acc[mt][nt][2];
                }
                if (cc + 1 < NL) {
                    Ls[r0 * LSTR + cc + 1]       = acc[mt][nt][1];
                    Ls[(r0 + 8) * LSTR + cc + 1] = acc[mt][nt][3];
                }
            }
    }
    __syncthreads();
    // pass 2: kh==1 warps accumulate
    if (kh == 1) {
#pragma unroll
        for (int mt = 0; mt < 2; ++mt)
#pragma unroll
            for (int nt = 0; nt < 5; ++nt) {
                int r0 = tg * 32 + mt * 16 + g;
                int cc = nt * 8 + t * 2;
                if (cc < NL) {
                    Ls[r0 * LSTR + cc]       += acc[mt][nt][0];
                    Ls[(r0 + 8) * LSTR + cc] += acc[mt][nt][2];
                }
                if (cc + 1 < NL) {
                    Ls[r0 * LSTR + cc + 1]       += acc[mt][nt][1];
                    Ls[(r0 + 8) * LSTR + cc + 1] += acc[mt][nt][3];
                }
            }
    }
    __syncthreads();

    // ---- dual softmax + store: threads 0..127 own one token each ----
    if (tid < BM) {
        const float corr = 1.000677f;   // tf32 RZ truncation bias compensation
        float sl[NS], fl[NF];
#pragma unroll
        for (int n = 0; n < NS; ++n) sl[n] = Ls[tid * LSTR + n] * corr + b_status[n];
#pragma unroll
        for (int n = 0; n < NF; ++n) fl[n] = Ls[tid * LSTR + NS + n] * corr + b_flight[n];

        float smax = sl[0];
#pragma unroll
        for (int n = 1; n < NS; ++n) smax = fmaxf(smax, sl[n]);
        float ssum = 0.f;
#pragma unroll
        for (int n = 0; n < NS; ++n) { sl[n] = __expf(sl[n] - smax); ssum += sl[n]; }
        float sinv = 1.f / ssum;
#pragma unroll
        for (int n = 0; n < NS; ++n) sl[n] *= sinv;

        float fm = fl[0];
#pragma unroll
        for (int n = 1; n < NF; ++n) fm = fmaxf(fm, fl[n]);
        float fsum = 0.f;
#pragma unroll
        for (int n = 0; n < NF; ++n) { fl[n] = __expf(fl[n] - fm); fsum += fl[n]; }
        float finv = 1.f / fsum;
#pragma unroll
        for (int n = 0; n < NF; ++n) fl[n] *= finv;

        const float book = sl[4], change = sl[3];
        long token = (long)blockIdx.x * BM + tid;
        if (token < ntok) {
            float* op = out + token * (long)OUTC;
            op[0] = sl[0];
            op[1] = sl[2];
            op[2] = sl[1];
#pragma unroll
            for (int j = 0; j < NF; ++j) {
                op[3 + j]  = book   * fl[j];
                op[33 + j] = change * fl[j];
            }
        }
    }
}

extern "C" void kernel_launch(void* const* d_in, const int* in_sizes, int n_in,
                              void* d_out, int out_size) {
    const float* embs     = (const float*)d_in[0];
    const float* W_status = (const float*)d_in[1];
    const float* b_status = (const float*)d_in[2];
    const float* W_flight = (const float*)d_in[3];
    const float* b_flight = (const float*)d_in[4];
    float* out = (float*)d_out;

    // pack weights into padded __device__ array (deterministic, capturable)
    pack_w_kernel<<<(NROWS * EMB + 255) / 256, 256>>>(W_status, W_flight);

    int ntok = in_sizes[0] / EMB;   // 65536
    int blocks = ntok / BM;         // 512
    aux2_ksplit_kernel<<<blocks, NTH>>>(embs, b_status, b_flight, out, ntok);
}

// round 16
// speedup vs baseline: 1.8974x; 1.8974x over previous
#include <cuda_runtime.h>
#include <cstdint>

// Skinny GEMM via mma.sync tf32: R8's proven cp.async A-ring + line-dense
// fragment-packed B.
// C[65536,40] = embs[65536,1024] @ W^T, W = [W_status(5); W_flight(30); 0pad]
// R16 thesis: runtime tracks the per-SM L1tex wavefront budget; the largest
// term was B-fragment LDGs touching 8 lines each (8 rows x 64B @ 4KB stride).
// Wpack stores W in fragment order: tile (kb,nt) = 8 rows x 16 cols = 512B
// contiguous, so each B LDG.128 is perfectly coalesced (4 lines, halved).
// A ring identical to R8 (wait -> read -> prefetch -> commit, barrier-free).
// Raw fp32 bits as tf32 (RZ truncate), bias cancelled by corr in epilogue.

#define EMB    1024
#define NS     5
#define NF     30
#define NL     35
#define OUTC   63
#define BM     128
#define LSTR   41
#define NTH    128
#define NKB    (EMB / 16)    // 64 k16 blocks
#define DEPTH  4

// ring: [warp][stage][r*32+lane] float4 slots = 4*4*128*16B = 32KB
#define STAGE_F4 128
#define WARP_F4  (DEPTH * STAGE_F4)

// packed B: [kb][nt][g][t] cells of 4 floats; tile (kb,nt) = 512B contiguous
__device__ float Wpack[NKB * 5 * 32 * 4];   // 160KB

__global__ void pack_w_kernel(const float* __restrict__ Ws,
                              const float* __restrict__ Wf) {
    int i = blockIdx.x * blockDim.x + threadIdx.x;   // 40960 floats
    if (i < NKB * 5 * 32 * 4) {
        int e    = i & 3;
        int cell = i >> 2;
        int t    = cell & 3;
        int g    = (cell >> 2) & 7;
        int rest = cell >> 5;
        int nt   = rest % 5;
        int kb   = rest / 5;
        int row  = nt * 8 + g;
        int col  = kb * 16 + t * 4 + e;
        float v = 0.0f;
        if (row < NS)      v = Ws[row * EMB + col];
        else if (row < NL) v = Wf[(row - NS) * EMB + col];
        Wpack[i] = v;
    }
}

__device__ __forceinline__ void mma8(float* c, const uint32_t* a, const uint32_t* b) {
    asm volatile(
        "mma.sync.aligned.m16n8k8.row.col.f32.tf32.tf32.f32 "
        "{%0,%1,%2,%3}, {%4,%5,%6,%7}, {%8,%9}, {%0,%1,%2,%3};"
        : "+f"(c[0]), "+f"(c[1]), "+f"(c[2]), "+f"(c[3])
        : "r"(a[0]), "r"(a[1]), "r"(a[2]), "r"(a[3]), "r"(b[0]), "r"(b[1]));
}
__device__ __forceinline__ void cp16s(uint32_t dst, const float* src) {
    asm volatile("cp.async.cg.shared.global [%0], [%1], 16;" :: "r"(dst), "l"(src));
}
__device__ __forceinline__ void cp_commit() { asm volatile("cp.async.commit_group;"); }
template<int N> __device__ __forceinline__ void cp_wait() {
    asm volatile("cp.async.wait_group %0;" :: "n"(N));
}

__global__ __launch_bounds__(NTH, 4) void aux2_packb_kernel(
    const float* __restrict__ embs,
    const float* __restrict__ b_status,
    const float* __restrict__ b_flight,
    float* __restrict__ out,
    int ntok)
{
    __shared__ __align__(16) char sraw[4 * WARP_F4 * 16];   // 32KB ring; Ls alias

    const int tid  = threadIdx.x;
    const int wid  = tid >> 5;
    const int lane = tid & 31;
    const int g    = lane >> 2;     // 0..7
    const int t    = lane & 3;      // 0..3
    const long tokw = (long)blockIdx.x * BM + wid * 32;

    // per-lane global A pointers: row tokw + r*8 + g, col 4t (advance 16/kb)
    const float* gptr[4];
#pragma unroll
    for (int r = 0; r < 4; ++r)
        gptr[r] = embs + (tokw + r * 8 + g) * EMB + 4 * t;

    uint32_t ringbase = (uint32_t)__cvta_generic_to_shared(sraw)
                      + (uint32_t)(wid * WARP_F4) * 16u;

    // packed B: lane-consecutive uint4 per (kb, nt) tile
    const uint4* Bp = reinterpret_cast<const uint4*>(Wpack) + lane;

    float acc[2][5][4];
#pragma unroll
    for (int mt = 0; mt < 2; ++mt)
#pragma unroll
        for (int nt = 0; nt < 5; ++nt)
#pragma unroll
            for (int i = 0; i < 4; ++i) acc[mt][nt][i] = 0.0f;

    // ---- prologue: fill stages 0..3, one commit group per stage ----
#pragma unroll
    for (int s = 0; s < DEPTH; ++s) {
#pragma unroll
        for (int r = 0; r < 4; ++r)
            cp16s(ringbase + (uint32_t)(s * STAGE_F4 + r * 32 + lane) * 16u,
                  gptr[r] + s * 16);
        cp_commit();
    }

    // ---- mainloop: wait -> read -> prefetch -> commit; no barriers ----
#pragma unroll 2
    for (int kb = 0; kb < NKB; ++kb) {
        const int s = kb & (DEPTH - 1);

        cp_wait<DEPTH - 1>();   // stage kb's group complete -> slot s readable

        uint4 v[4];
#pragma unroll
        for (int r = 0; r < 4; ++r) {
            uint32_t sa = ringbase + (uint32_t)(s * STAGE_F4 + r * 32 + lane) * 16u;
            asm volatile("ld.shared.v4.u32 {%0,%1,%2,%3}, [%4];"
                         : "=r"(v[r].x), "=r"(v[r].y), "=r"(v[r].z), "=r"(v[r].w)
                         : "r"(sa));
        }

        // refill dead slot s with stage kb+DEPTH (LDS above already latched)
        if (kb + DEPTH < NKB) {
#pragma unroll
            for (int r = 0; r < 4; ++r)
                cp16s(ringbase + (uint32_t)(s * STAGE_F4 + r * 32 + lane) * 16u,
                      gptr[r] + (kb + DEPTH) * 16);
        }
        cp_commit();            // unconditional: uniform group accounting

        // B: 5 perfectly-coalesced LDG.128 (tile = 512B contiguous)
        uint4 b[5];
#pragma unroll
        for (int nt = 0; nt < 5; ++nt) b[nt] = Bp[(kb * 5 + nt) * 32];

        uint32_t af0[2][4] = {
            { v[0].x, v[1].x, v[0].y, v[1].y },
            { v[2].x, v[3].x, v[2].y, v[3].y } };
        uint32_t af1[2][4] = {
            { v[0].z, v[1].z, v[0].w, v[1].w },
            { v[2].z, v[3].z, v[2].w, v[3].w } };

#pragma unroll
        for (int nt = 0; nt < 5; ++nt) {
            uint32_t bf0[2] = { b[nt].x, b[nt].y };
            uint32_t bf1[2] = { b[nt].z, b[nt].w };
#pragma unroll
            for (int mt = 0; mt < 2; ++mt) {
                mma8(acc[mt][nt], af0[mt], bf0);
                mma8(acc[mt][nt], af1[mt], bf1);
            }
        }
    }

    cp_wait<0>();
    __syncthreads();          // ring dead; alias as logits buffer

    // ---- epilogue: fragments -> logits smem ----
    float* Ls = reinterpret_cast<float*>(sraw);   // 128*41*4 = 21KB < 32KB
#pragma unroll
    for (int mt = 0; mt < 2; ++mt)
#pragma unroll
        for (int nt = 0; nt < 5; ++nt) {
            int r0 = wid * 32 + mt * 16 + g;
            int cc = nt * 8 + t * 2;
            if (cc < NL) {
                Ls[r0 * LSTR + cc]       = acc[mt][nt][0];
                Ls[(r0 + 8) * LSTR + cc] = acc[mt][nt][2];
            }
            if (cc + 1 < NL) {
                Ls[r0 * LSTR + cc + 1]       = acc[mt][nt][1];
                Ls[(r0 + 8) * LSTR + cc + 1] = acc[mt][nt][3];
            }
        }
    __syncthreads();

    // ---- per-thread dual softmax + store (thread tid = token) ----
    {
        const float corr = 1.000677f;   // tf32 RZ truncation bias compensation
        float sl[NS], fl[NF];
#pragma unroll
        for (int n = 0; n < NS; ++n) sl[n] = Ls[tid * LSTR + n] * corr + b_status[n];
#pragma unroll
        for (int n = 0; n < NF; ++n) fl[n] = Ls[tid * LSTR + NS + n] * corr + b_flight[n];

        float smax = sl[0];
#pragma unroll
        for (int n = 1; n < NS; ++n) smax = fmaxf(smax, sl[n]);
        float ssum = 0.f;
#pragma unroll
        for (int n = 0; n < NS; ++n) { sl[n] = __expf(sl[n] - smax); ssum += sl[n]; }
        float sinv = 1.f / ssum;
#pragma unroll
        for (int n = 0; n < NS; ++n) sl[n] *= sinv;

        float fm = fl[0];
#pragma unroll
        for (int n = 1; n < NF; ++n) fm = fmaxf(fm, fl[n]);
        float fsum = 0.f;
#pragma unroll
        for (int n = 0; n < NF; ++n) { fl[n] = __expf(fl[n] - fm); fsum += fl[n]; }
        float finv = 1.f / fsum;
#pragma unroll
        for (int n = 0; n < NF; ++n) fl[n] *= finv;

        const float book = sl[4], change = sl[3];
        long token = (long)blockIdx.x * BM + tid;
        if (token < ntok) {
            float* op = out + token * (long)OUTC;
            op[0] = sl[0];
            op[1] = sl[2];
            op[2] = sl[1];
#pragma unroll
            for (int j = 0; j < NF; ++j) {
                op[3 + j]  = book   * fl[j];
                op[33 + j] = change * fl[j];
            }
        }
    }
}

extern "C" void kernel_launch(void* const* d_in, const int* in_sizes, int n_in,
                              void* d_out, int out_size) {
    const float* embs     = (const float*)d_in[0];
    const float* W_status = (const float*)d_in[1];
    const float* b_status = (const float*)d_in[2];
    const float* W_flight = (const float*)d_in[3];
    const float* b_flight = (const float*)d_in[4];
    float* out = (float*)d_out;

    // pack weights into fragment-ordered __device__ array (capturable)
    pack_w_kernel<<<(NKB * 5 * 32 * 4 + 255) / 256, 256>>>(W_status, W_flight);

    int ntok = in_sizes[0] / EMB;   // 65536
    int blocks = ntok / BM;         // 512
    aux2_packb_kernel<<<blocks, NTH>>>(embs, b_status, b_flight, out, ntok);
}